// round 15
// baseline (speedup 1.0000x reference)
#include <cuda_runtime.h>
#include <cuda_fp16.h>
#include <math.h>
#include <float.h>
#include <stdint.h>

// Problem constants
#define BB   4
#define SS   2048
#define DD   1024
#define HH   16
#define DH   64
#define MROWS (BB*SS)      // 8192

// ---------------------------------------------------------------------------
// Scratch (allocation-free rule: __device__ globals)
// ---------------------------------------------------------------------------
#define NEL ((size_t)MROWS*DD)               // 8M elements
__device__ __align__(16) __half g_qf[NEL];           // fp16(Q_batch)
__device__ __align__(16) __half g_kf[NEL];           // fp16(K_batch)
__device__ __align__(16) __half g_vf[NEL];           // fp16(V_batch)
__device__ __align__(16) __half g_pq[NEL];           // projected q (pre-scaled log2e/8)
__device__ __align__(16) __half g_pk[NEL];
__device__ __align__(16) __half g_pv[NEL];
__device__ __align__(16) __half g_ch[NEL];           // attn out fp16, concat layout
__device__ __align__(16) __half g_wt[4][DD*DD];      // W^T fp16 (wt[0] scaled log2e/8)

// ---------------------------------------------------------------------------
// helpers
// ---------------------------------------------------------------------------
__device__ __forceinline__ uint32_t smem_u32(const void* p) {
    uint32_t a;
    asm("{ .reg .u64 t; cvta.to.shared.u64 t, %1; cvt.u32.u64 %0, t; }" : "=r"(a) : "l"(p));
    return a;
}
__device__ __forceinline__ void cp16(uint32_t dst, const void* src) {
    asm volatile("cp.async.cg.shared.global [%0], [%1], 16;" :: "r"(dst), "l"(src));
}
#define CP_COMMIT() asm volatile("cp.async.commit_group;" ::: "memory")
#define CP_WAIT2()  asm volatile("cp.async.wait_group 2;" ::: "memory")
#define CP_WAIT1()  asm volatile("cp.async.wait_group 1;" ::: "memory")
#define CP_WAIT0()  asm volatile("cp.async.wait_group 0;" ::: "memory")

__device__ __forceinline__ void ldsm4(uint32_t& r0, uint32_t& r1, uint32_t& r2, uint32_t& r3,
                                      uint32_t addr) {
    asm volatile("ldmatrix.sync.aligned.m8n8.x4.shared.b16 {%0,%1,%2,%3}, [%4];"
                 : "=r"(r0), "=r"(r1), "=r"(r2), "=r"(r3) : "r"(addr));
}
__device__ __forceinline__ void ldsm4t(uint32_t& r0, uint32_t& r1, uint32_t& r2, uint32_t& r3,
                                       uint32_t addr) {
    asm volatile("ldmatrix.sync.aligned.m8n8.x4.trans.shared.b16 {%0,%1,%2,%3}, [%4];"
                 : "=r"(r0), "=r"(r1), "=r"(r2), "=r"(r3) : "r"(addr));
}
__device__ __forceinline__ void mma_f16(float* c, const uint32_t* a, const uint32_t* b) {
    asm volatile(
        "mma.sync.aligned.m16n8k16.row.col.f32.f16.f16.f32 "
        "{%0,%1,%2,%3}, {%4,%5,%6,%7}, {%8,%9}, {%0,%1,%2,%3};"
        : "+f"(c[0]), "+f"(c[1]), "+f"(c[2]), "+f"(c[3])
        : "r"(a[0]), "r"(a[1]), "r"(a[2]), "r"(a[3]), "r"(b[0]), "r"(b[1]));
}
// single-instruction pack: d[15:0]=f16(lo), d[31:16]=f16(hi)
__device__ __forceinline__ uint32_t pack_f16(float lo, float hi) {
    uint32_t r;
    asm("cvt.rn.f16x2.f32 %0, %1, %2;" : "=r"(r) : "f"(hi), "f"(lo));
    return r;
}

// ---------------------------------------------------------------------------
// valid_lens may physically be int32 (jax x64 disabled) or int64.
// ---------------------------------------------------------------------------
__device__ __forceinline__ int load_valid_len(const int* p, int b) {
    bool is64 = (p[1] == 0) && (p[3] == 0);
    int v = is64 ? p[2 * b] : p[b];
    if (v < 0) v = 0;
    if (v > SS) v = SS;
    return v;
}

// ---------------------------------------------------------------------------
// Fused fp32 -> fp16 convert for Q, K, V inputs. z selects tensor.
// ---------------------------------------------------------------------------
__global__ __launch_bounds__(256) void cvt3_kernel(
    const float4* __restrict__ inQ, const float4* __restrict__ inK,
    const float4* __restrict__ inV)
{
    const int z = blockIdx.z;
    const float4* in = (z == 0) ? inQ : (z == 1) ? inK : inV;
    ushort4* hi = (ushort4*)((z == 0) ? g_qf : (z == 1) ? g_kf : g_vf);
    int i = blockIdx.x * 256 + threadIdx.x;
    float4 v = in[i];
    hi[i] = make_ushort4(
        __half_as_ushort(__float2half_rn(v.x)),
        __half_as_ushort(__float2half_rn(v.y)),
        __half_as_ushort(__float2half_rn(v.z)),
        __half_as_ushort(__float2half_rn(v.w)));
}

// ---------------------------------------------------------------------------
// Fused W[k,n] -> wt[n,k] fp16 transpose.
// z==0 (Wq) pre-scaled by log2(e)/sqrt(DH) so attention works in exp2 domain.
// ---------------------------------------------------------------------------
__global__ __launch_bounds__(256) void wsplit_kernel(
    const float* __restrict__ W0, const float* __restrict__ W1,
    const float* __restrict__ W2, const float* __restrict__ W3)
{
    __shared__ float tile[32][33];
    const int z = blockIdx.z;
    const float* W = (z == 0) ? W0 : (z == 1) ? W1 : (z == 2) ? W2 : W3;
    const float sc = (z == 0) ? 0.125f * 1.4426950408889634f : 1.0f;
    __half* th = g_wt[z];
    const int tx = threadIdx.x, ty = threadIdx.y;      // (32, 8)
    const int bk = blockIdx.x * 32, bn = blockIdx.y * 32;
#pragma unroll
    for (int i = 0; i < 4; i++)
        tile[ty + 8 * i][tx] = W[(size_t)(bk + ty + 8 * i) * DD + bn + tx];
    __syncthreads();
#pragma unroll
    for (int i = 0; i < 4; i++) {
        float f = tile[tx][ty + 8 * i] * sc;
        th[(size_t)(bn + ty + 8 * i) * DD + bk + tx] = __float2half_rn(f);
    }
}

// ---------------------------------------------------------------------------
// Tensor-core GEMM core (mma.sync fp16), templated on number of A terms.
// NT=1: C = Ah*Bh.  NT=2: C = Ah*Bh + Al*Bh. 3-stage cp.async pipeline.
// mode 0: C fp32 row-major. mode 3: fp16 single, head-major.
// ---------------------------------------------------------------------------
#define PADK    72
#define TILE_B  (128*PADK*2)        // 18432
#define SMEM_PROJ (3*2*TILE_B)      // 110592

template<int NT>
__device__ __forceinline__ void gemm_core(
    uint32_t sb,
    const uint4* __restrict__ pAh, const uint4* __restrict__ pAl,
    const uint4* __restrict__ pBh,
    float* __restrict__ C, __half* __restrict__ Chi,
    int mode, int bm, int bn)
{
    constexpr uint32_t OFF_B   = (uint32_t)NT * TILE_B;
    constexpr uint32_t STAGE_B = (uint32_t)(NT + 1) * TILE_B;

    const int tid  = threadIdx.x;
    const int wid  = tid >> 5;
    const int lane = tid & 31;

    const int lrow = tid >> 3;
    const int lc8  = tid & 7;

    float acc[4][4][4];
#pragma unroll
    for (int mt = 0; mt < 4; mt++)
#pragma unroll
        for (int nt = 0; nt < 4; nt++)
#pragma unroll
            for (int e = 0; e < 4; e++) acc[mt][nt][e] = 0.f;

    const int mbase = (wid & 1) * 64;
    const int nbase = (wid >> 1) * 32;
    const int aRow  = mbase + (lane & 15);
    const int aKoff = (lane >> 4) * 8;
    const int bRow  = nbase + (lane & 7) + ((lane >> 4) & 1) * 8;
    const int bKoff = ((lane >> 3) & 1) * 8;
    const uint32_t aOffBase = (uint32_t)((aRow * PADK + aKoff) * 2);
    const uint32_t bOffBase = (uint32_t)((bRow * PADK + bKoff) * 2);

    auto issue = [&](int c, int st) {
        const uint32_t stb = sb + (uint32_t)st * STAGE_B;
#pragma unroll
        for (int i = 0; i < 4; i++) {
            int row = lrow + i * 32;
            uint32_t so = stb + (uint32_t)((row * PADK + lc8 * 8) * 2);
            size_t ai = (size_t)(bm + row) * 128 + c * 8 + lc8;
            size_t bi = (size_t)(bn + row) * 128 + c * 8 + lc8;
            cp16(so, pAh + ai);
            if (NT == 2) cp16(so + TILE_B, pAl + ai);
            cp16(so + OFF_B, pBh + bi);
        }
        CP_COMMIT();
    };

    issue(0, 0);
    issue(1, 1);

    for (int c = 0; c < 16; c++) {
        if (c < 15) { CP_WAIT1(); } else { CP_WAIT0(); }
        __syncthreads();
        if (c + 2 < 16) issue(c + 2, (c + 2) % 3);

        const uint32_t stb = sb + (uint32_t)(c % 3) * STAGE_B;
#pragma unroll
        for (int ks = 0; ks < 4; ks++) {
            const uint32_t kb = (uint32_t)(ks * 16 * 2);
            uint32_t bh[8];
            ldsm4(bh[0], bh[1], bh[2], bh[3], stb + OFF_B + bOffBase + kb);
            ldsm4(bh[4], bh[5], bh[6], bh[7], stb + OFF_B + bOffBase + kb + 16 * PADK * 2);
#pragma unroll
            for (int mt = 0; mt < 4; mt++) {
                const uint32_t aoff = aOffBase + (uint32_t)(mt * 16 * PADK * 2) + kb;
                uint32_t ah[4];
                ldsm4(ah[0], ah[1], ah[2], ah[3], stb + aoff);
                uint32_t al[4];
                if (NT == 2)
                    ldsm4(al[0], al[1], al[2], al[3], stb + TILE_B + aoff);
#pragma unroll
                for (int nt = 0; nt < 4; nt++) {
                    const uint32_t* bfh = &bh[(nt & 1) ? ((nt >> 1) * 4 + 2) : ((nt >> 1) * 4)];
                    mma_f16(acc[mt][nt], ah, bfh);
                    if (NT == 2) mma_f16(acc[mt][nt], al, bfh);
                }
            }
        }
    }

    const int rl = lane >> 2;
    const int cl = (lane & 3) * 2;
#pragma unroll
    for (int mt = 0; mt < 4; mt++) {
#pragma unroll
        for (int nt = 0; nt < 4; nt++) {
            const int row0 = bm + mbase + mt * 16 + rl;
            const int row1 = row0 + 8;
            const int colg = bn + nbase + nt * 8 + cl;
            float v0 = acc[mt][nt][0], v1 = acc[mt][nt][1];
            float v2 = acc[mt][nt][2], v3 = acc[mt][nt][3];
            if (mode == 0) {
                *(float2*)(C + (size_t)row0 * DD + colg) = make_float2(v0, v1);
                *(float2*)(C + (size_t)row1 * DD + colg) = make_float2(v2, v3);
            } else {
                const int h = colg >> 6, dh0 = colg & 63;
                const int b0 = row0 >> 11, s0 = row0 & 2047;
                const int b1 = row1 >> 11, s1 = row1 & 2047;
                size_t o0 = (((size_t)(b0 * HH + h)) * SS + s0) * DH + dh0;
                size_t o1 = (((size_t)(b1 * HH + h)) * SS + s1) * DH + dh0;
                *(uint32_t*)(Chi + o0) = pack_f16(v0, v1);
                *(uint32_t*)(Chi + o1) = pack_f16(v2, v3);
            }
        }
    }
}

// Fused projection GEMM (single-term fp16): z = 0 (Q), 1 (K), 2 (V).
__global__ __launch_bounds__(256) void gemm_proj(void)
{
    extern __shared__ char smem[];
    const uint32_t sb = smem_u32(smem);
    const int z = blockIdx.z;
    const uint4* pAh = (const uint4*)((z == 0) ? g_qf : (z == 1) ? g_kf : g_vf);
    const uint4* pBh = (const uint4*)g_wt[z];
    __half* Chi = (z == 0) ? g_pq : (z == 1) ? g_pk : g_pv;
    gemm_core<1>(sb, pAh, nullptr, pBh, nullptr, Chi, 3,
                 blockIdx.y * 128, blockIdx.x * 128);
}

// Output projection GEMM (single-term fp16 A = attention output).
__global__ __launch_bounds__(256) void gemm_out(float* __restrict__ C)
{
    extern __shared__ char smem[];
    const uint32_t sb = smem_u32(smem);
    gemm_core<1>(sb, (const uint4*)g_ch, nullptr, (const uint4*)g_wt[3],
                 C, nullptr, 0, blockIdx.y * 128, blockIdx.x * 128);
}

// ---------------------------------------------------------------------------
// Flash attention, mma.sync fp16, single-term QK and PV. exp2 domain
// (log2e folded into Wq). Row-sum l computed by an extra n=8 MMA against an
// analytic ones B-fragment (lane<4 ? half2(1,1) : 0) — no scalar reduction.
// 128 threads, ATQ=64, 3-stage KV ring, Q aliases stage 2. 4 CTAs/SM.
// Grid: x = (b,h)  [mixes valid_lens within each wave], y = q-block.
// ---------------------------------------------------------------------------
#define ATQ  64
#define NTHR 128
#define ATK  64
#define APAD 72
#define AT_TILE (ATK*APAD*2)          // 9216
#define AST_B    (2*AT_TILE)          // 18432 per stage (K, V)
#define AKH 0
#define AVH (1*AT_TILE)
#define AQ_OFF   (2*AST_B)            // Q lives in stage 2's region
#define SMEM_ATTN (3*AST_B)           // 55296 -> 4 CTAs/SM

__global__ __launch_bounds__(NTHR) void attn_tc(
    const int* __restrict__ valid_lens_raw, __half* __restrict__ outh)
{
    extern __shared__ char smem[];
    const uint32_t sb = smem_u32(smem);
    const int tid  = threadIdx.x;
    const int w    = tid >> 5;
    const int lane = tid & 31;
    const int bh   = blockIdx.x;
    const int b    = bh >> 4;
    const int h    = bh & 15;
    const int qbase = blockIdx.y * ATQ;

    const int L = load_valid_len(valid_lens_raw, b);
    const bool uniform = (L == 0);
    const int Leff = uniform ? SS : L;
    const int ntiles = (Leff + ATK - 1) >> 6;

    const uint4* pQ = (const uint4*)g_pq;
    const uint4* pK = (const uint4*)g_pk;
    const uint4* pV = (const uint4*)g_pv;

    // ---- issue Q load into stage-2 region ----
    {
#pragma unroll
        for (int i = 0; i < 4; i++) {
            int g = tid + i * NTHR;
            int row = g >> 3, c8 = g & 7;
            size_t gi = ((size_t)bh * SS + qbase + row) * 8 + c8;
            cp16(sb + AQ_OFF + (uint32_t)((row * APAD + c8 * 8) * 2), pQ + gi);
        }
        CP_COMMIT();
    }

    auto issueKV = [&](int t, int st) {
        const uint32_t stb = sb + (uint32_t)st * AST_B;
        const int kb = t * ATK;
#pragma unroll
        for (int i = 0; i < 4; i++) {
            int g = tid + i * NTHR;
            int row = g >> 3, c8 = g & 7;
            size_t gi = ((size_t)bh * SS + kb + row) * 8 + c8;
            uint32_t so = (uint32_t)((row * APAD + c8 * 8) * 2);
            cp16(stb + AKH + so, pK + gi);
            cp16(stb + AVH + so, pV + gi);
        }
        CP_COMMIT();
    };

    issueKV(0, 0);
    if (ntiles > 1) { issueKV(1, 1); CP_WAIT2(); } else { CP_WAIT1(); }
    __syncthreads();

    // ---- Q fragments into registers (before stage 2 is overwritten) ----
    const int gid = lane >> 2;
    const int qrl = lane & 3;
    uint32_t qf[4][4];
    {
        const int aRow = w * 16 + (lane & 15);
        const uint32_t aoff0 = (uint32_t)((aRow * APAD + (lane >> 4) * 8) * 2);
#pragma unroll
        for (int ks = 0; ks < 4; ks++)
            ldsm4(qf[ks][0], qf[ks][1], qf[ks][2], qf[ks][3],
                  sb + AQ_OFF + aoff0 + (uint32_t)(ks * 16 * 2));
    }

    // analytic B-fragment of 16x8 "ones in column 0" matrix
    uint32_t onesb[2];
    onesb[0] = onesb[1] = (lane < 4) ? 0x3C003C00u : 0u;

    float O[8][4];
#pragma unroll
    for (int nt = 0; nt < 8; nt++)
#pragma unroll
        for (int e = 0; e < 4; e++) O[nt][e] = 0.f;
    float Ol[4] = {0.f, 0.f, 0.f, 0.f};     // col 0 = row-sum l
    float m0 = -FLT_MAX, m1 = -FLT_MAX;

    const int kRow = (lane & 7) + ((lane >> 4) & 1) * 8;
    const int kKof = ((lane >> 3) & 1) * 8;
    const int vRow = lane & 15;
    const int vCol = (lane >> 4) * 8;

    for (int t = 0; t < ntiles; t++) {
        if (t < ntiles - 1) { CP_WAIT1(); } else { CP_WAIT0(); }
        __syncthreads();
        if (t + 2 < ntiles) issueKV(t + 2, (t + 2) % 3);

        const uint32_t stb = sb + (uint32_t)(t % 3) * AST_B;

        // ---- scores (pre-scaled by folded Wq: log2e/8) ----
        float c[8][4];
#pragma unroll
        for (int nt = 0; nt < 8; nt++)
#pragma unroll
            for (int e = 0; e < 4; e++) c[nt][e] = 0.f;

        if (!uniform) {
#pragma unroll
            for (int ks = 0; ks < 4; ks++) {
                const uint32_t kb = (uint32_t)(ks * 16 * 2);
#pragma unroll
                for (int g = 0; g < 4; g++) {
                    const uint32_t boff = (uint32_t)(((g * 16 + kRow) * APAD + kKof) * 2) + kb;
                    uint32_t kh4[4];
                    ldsm4(kh4[0], kh4[1], kh4[2], kh4[3], stb + AKH + boff);
                    mma_f16(c[2 * g],     qf[ks], kh4 + 0);
                    mma_f16(c[2 * g + 1], qf[ks], kh4 + 2);
                }
            }
        }

        // ---- mask (last partial tile only) ----
        const int tilebase = t * ATK;
        if (tilebase + ATK > Leff) {
#pragma unroll
            for (int nt = 0; nt < 8; nt++) {
#pragma unroll
                for (int e = 0; e < 4; e++) {
                    int key = tilebase + nt * 8 + qrl * 2 + (e & 1);
                    if (key >= Leff) c[nt][e] = -FLT_MAX;
                }
            }
        }

        // ---- online softmax (base-2) ----
        float rm0 = -FLT_MAX, rm1 = -FLT_MAX;
#pragma unroll
        for (int nt = 0; nt < 8; nt++) {
            rm0 = fmaxf(rm0, fmaxf(c[nt][0], c[nt][1]));
            rm1 = fmaxf(rm1, fmaxf(c[nt][2], c[nt][3]));
        }
#pragma unroll
        for (int off = 1; off <= 2; off <<= 1) {
            rm0 = fmaxf(rm0, __shfl_xor_sync(0xffffffffu, rm0, off));
            rm1 = fmaxf(rm1, __shfl_xor_sync(0xffffffffu, rm1, off));
        }
        const float mn0 = fmaxf(m0, rm0);
        const float mn1 = fmaxf(m1, rm1);
        const float al0 = exp2f(m0 - mn0);
        const float al1 = exp2f(m1 - mn1);
        m0 = mn0; m1 = mn1;

        uint32_t ph01[8], ph23[8];
#pragma unroll
        for (int nt = 0; nt < 8; nt++) {
            ph01[nt] = pack_f16(exp2f(c[nt][0] - mn0), exp2f(c[nt][1] - mn0));
            ph23[nt] = pack_f16(exp2f(c[nt][2] - mn1), exp2f(c[nt][3] - mn1));
        }
#pragma unroll
        for (int nt = 0; nt < 8; nt++) {
            O[nt][0] *= al0; O[nt][1] *= al0;
            O[nt][2] *= al1; O[nt][3] *= al1;
        }
        Ol[0] *= al0; Ol[1] *= al0; Ol[2] *= al1; Ol[3] *= al1;

        // ---- O += P V ; Ol += P 1 ----
#pragma unroll
        for (int tk = 0; tk < 4; tk++) {
            uint32_t ah[4] = {ph01[2 * tk], ph23[2 * tk], ph01[2 * tk + 1], ph23[2 * tk + 1]};
            mma_f16(Ol, ah, onesb);
#pragma unroll
            for (int g = 0; g < 4; g++) {
                const uint32_t voff = (uint32_t)(((tk * 16 + vRow) * APAD + g * 16 + vCol) * 2);
                uint32_t vh4[4];
                ldsm4t(vh4[0], vh4[1], vh4[2], vh4[3], stb + AVH + voff);
                mma_f16(O[2 * g],     ah, vh4 + 0);
                mma_f16(O[2 * g + 1], ah, vh4 + 2);
            }
        }
    }

    // ---- recover l (col 0 lives in quad-lane 0), normalize, store fp16 ----
    const float l0 = __shfl_sync(0xffffffffu, Ol[0], lane & 28);
    const float l1 = __shfl_sync(0xffffffffu, Ol[2], lane & 28);
    const float inv0 = 1.f / l0;
    const float inv1 = 1.f / l1;
    const int q0g = qbase + w * 16 + gid;
    const int q1g = q0g + 8;
#pragma unroll
    for (int nt = 0; nt < 8; nt++) {
        const int col = h * 64 + nt * 8 + qrl * 2;
        size_t o0 = ((size_t)(b * SS + q0g)) * DD + col;
        size_t o1 = ((size_t)(b * SS + q1g)) * DD + col;
        *(uint32_t*)(outh + o0) = pack_f16(O[nt][0] * inv0, O[nt][1] * inv0);
        *(uint32_t*)(outh + o1) = pack_f16(O[nt][2] * inv1, O[nt][3] * inv1);
    }
}

// ---------------------------------------------------------------------------
extern "C" void kernel_launch(void* const* d_in, const int* in_sizes, int n_in,
                              void* d_out, int out_size)
{
    const float* Q  = (const float*)d_in[0];
    const float* Km = (const float*)d_in[1];
    const float* V  = (const float*)d_in[2];
    const int*   vl = (const int*)d_in[3];
    const float* Wq = (const float*)d_in[4];
    const float* Wk = (const float*)d_in[5];
    const float* Wv = (const float*)d_in[6];
    const float* Wo = (const float*)d_in[7];
    float* out = (float*)d_out;

    __half *ch;
    cudaGetSymbolAddress((void**)&ch, g_ch);

    cudaFuncSetAttribute(gemm_proj, cudaFuncAttributeMaxDynamicSharedMemorySize, SMEM_PROJ);
    cudaFuncSetAttribute(gemm_out,  cudaFuncAttributeMaxDynamicSharedMemorySize, SMEM_PROJ);
    cudaFuncSetAttribute(attn_tc,   cudaFuncAttributeMaxDynamicSharedMemorySize, SMEM_ATTN);

    dim3 gCvt((unsigned)(NEL / 4 / 256), 1, 3);
    cvt3_kernel<<<gCvt, 256>>>((const float4*)Q, (const float4*)Km, (const float4*)V);

    dim3 gW(32, 32, 4), bW(32, 8);
    wsplit_kernel<<<gW, bW>>>(Wq, Wk, Wv, Wo);

    dim3 gProj(DD / 128, MROWS / 128, 3);                 // (8, 64, 3)
    gemm_proj<<<gProj, 256, SMEM_PROJ>>>();

    dim3 gAttn(BB * HH, SS / ATQ);                        // (64, 32)
    attn_tc<<<gAttn, NTHR, SMEM_ATTN>>>(vl, ch);

    dim3 gOut(DD / 128, MROWS / 128);                     // (8, 64)
    gemm_out<<<gOut, 256, SMEM_PROJ>>>(out);
}

// round 16
// speedup vs baseline: 1.0888x; 1.0888x over previous
#include <cuda_runtime.h>
#include <cuda_fp16.h>
#include <math.h>
#include <float.h>
#include <stdint.h>

// Problem constants
#define BB   4
#define SS   2048
#define DD   1024
#define HH   16
#define DH   64
#define MROWS (BB*SS)      // 8192

// ---------------------------------------------------------------------------
// Scratch (allocation-free rule: __device__ globals)
// ---------------------------------------------------------------------------
#define NEL ((size_t)MROWS*DD)               // 8M elements
__device__ __align__(16) __half g_qf[NEL];           // fp16(Q_batch)
__device__ __align__(16) __half g_kf[NEL];           // fp16(K_batch)
__device__ __align__(16) __half g_vf[NEL];           // fp16(V_batch)
__device__ __align__(16) __half g_pq[NEL];           // projected q (pre-scaled log2e/8)
__device__ __align__(16) __half g_pk[NEL];
__device__ __align__(16) __half g_pv[NEL];
__device__ __align__(16) __half g_ch[NEL];           // attn out fp16, concat layout
__device__ __align__(16) __half g_wt[4][DD*DD];      // W^T fp16 (wt[0] scaled log2e/8)

// ---------------------------------------------------------------------------
// helpers
// ---------------------------------------------------------------------------
__device__ __forceinline__ uint32_t smem_u32(const void* p) {
    uint32_t a;
    asm("{ .reg .u64 t; cvta.to.shared.u64 t, %1; cvt.u32.u64 %0, t; }" : "=r"(a) : "l"(p));
    return a;
}
__device__ __forceinline__ void cp16(uint32_t dst, const void* src) {
    asm volatile("cp.async.cg.shared.global [%0], [%1], 16;" :: "r"(dst), "l"(src));
}
#define CP_COMMIT() asm volatile("cp.async.commit_group;" ::: "memory")
#define CP_WAIT2()  asm volatile("cp.async.wait_group 2;" ::: "memory")
#define CP_WAIT1()  asm volatile("cp.async.wait_group 1;" ::: "memory")
#define CP_WAIT0()  asm volatile("cp.async.wait_group 0;" ::: "memory")

__device__ __forceinline__ void ldsm4(uint32_t& r0, uint32_t& r1, uint32_t& r2, uint32_t& r3,
                                      uint32_t addr) {
    asm volatile("ldmatrix.sync.aligned.m8n8.x4.shared.b16 {%0,%1,%2,%3}, [%4];"
                 : "=r"(r0), "=r"(r1), "=r"(r2), "=r"(r3) : "r"(addr));
}
__device__ __forceinline__ void ldsm4t(uint32_t& r0, uint32_t& r1, uint32_t& r2, uint32_t& r3,
                                       uint32_t addr) {
    asm volatile("ldmatrix.sync.aligned.m8n8.x4.trans.shared.b16 {%0,%1,%2,%3}, [%4];"
                 : "=r"(r0), "=r"(r1), "=r"(r2), "=r"(r3) : "r"(addr));
}
__device__ __forceinline__ void mma_f16(float* c, const uint32_t* a, const uint32_t* b) {
    asm volatile(
        "mma.sync.aligned.m16n8k16.row.col.f32.f16.f16.f32 "
        "{%0,%1,%2,%3}, {%4,%5,%6,%7}, {%8,%9}, {%0,%1,%2,%3};"
        : "+f"(c[0]), "+f"(c[1]), "+f"(c[2]), "+f"(c[3])
        : "r"(a[0]), "r"(a[1]), "r"(a[2]), "r"(a[3]), "r"(b[0]), "r"(b[1]));
}
// single-instruction pack: d[15:0]=f16(lo), d[31:16]=f16(hi)
__device__ __forceinline__ uint32_t pack_f16(float lo, float hi) {
    uint32_t r;
    asm("cvt.rn.f16x2.f32 %0, %1, %2;" : "=r"(r) : "f"(hi), "f"(lo));
    return r;
}

// ---------------------------------------------------------------------------
// valid_lens may physically be int32 (jax x64 disabled) or int64.
// ---------------------------------------------------------------------------
__device__ __forceinline__ int load_valid_len(const int* p, int b) {
    bool is64 = (p[1] == 0) && (p[3] == 0);
    int v = is64 ? p[2 * b] : p[b];
    if (v < 0) v = 0;
    if (v > SS) v = SS;
    return v;
}

// ---------------------------------------------------------------------------
// Fused fp32 -> fp16 convert for Q, K, V inputs. z selects tensor.
// ---------------------------------------------------------------------------
__global__ __launch_bounds__(256) void cvt3_kernel(
    const float4* __restrict__ inQ, const float4* __restrict__ inK,
    const float4* __restrict__ inV)
{
    const int z = blockIdx.z;
    const float4* in = (z == 0) ? inQ : (z == 1) ? inK : inV;
    ushort4* hi = (ushort4*)((z == 0) ? g_qf : (z == 1) ? g_kf : g_vf);
    int i = blockIdx.x * 256 + threadIdx.x;
    float4 v = in[i];
    hi[i] = make_ushort4(
        __half_as_ushort(__float2half_rn(v.x)),
        __half_as_ushort(__float2half_rn(v.y)),
        __half_as_ushort(__float2half_rn(v.z)),
        __half_as_ushort(__float2half_rn(v.w)));
}

// ---------------------------------------------------------------------------
// Fused W[k,n] -> wt[n,k] fp16 transpose.
// z==0 (Wq) pre-scaled by log2(e)/sqrt(DH) so attention works in exp2 domain.
// ---------------------------------------------------------------------------
__global__ __launch_bounds__(256) void wsplit_kernel(
    const float* __restrict__ W0, const float* __restrict__ W1,
    const float* __restrict__ W2, const float* __restrict__ W3)
{
    __shared__ float tile[32][33];
    const int z = blockIdx.z;
    const float* W = (z == 0) ? W0 : (z == 1) ? W1 : (z == 2) ? W2 : W3;
    const float sc = (z == 0) ? 0.125f * 1.4426950408889634f : 1.0f;
    __half* th = g_wt[z];
    const int tx = threadIdx.x, ty = threadIdx.y;      // (32, 8)
    const int bk = blockIdx.x * 32, bn = blockIdx.y * 32;
#pragma unroll
    for (int i = 0; i < 4; i++)
        tile[ty + 8 * i][tx] = W[(size_t)(bk + ty + 8 * i) * DD + bn + tx];
    __syncthreads();
#pragma unroll
    for (int i = 0; i < 4; i++) {
        float f = tile[tx][ty + 8 * i] * sc;
        th[(size_t)(bn + ty + 8 * i) * DD + bk + tx] = __float2half_rn(f);
    }
}

// ---------------------------------------------------------------------------
// Tensor-core GEMM core (mma.sync fp16), templated on number of A terms.
// NT=1: C = Ah*Bh.  NT=2: C = Ah*Bh + Al*Bh. 3-stage cp.async pipeline.
// mode 0: C fp32 row-major. mode 3: fp16 single, head-major.
// ---------------------------------------------------------------------------
#define PADK    72
#define TILE_B  (128*PADK*2)        // 18432
#define SMEM_PROJ (3*2*TILE_B)      // 110592

template<int NT>
__device__ __forceinline__ void gemm_core(
    uint32_t sb,
    const uint4* __restrict__ pAh, const uint4* __restrict__ pAl,
    const uint4* __restrict__ pBh,
    float* __restrict__ C, __half* __restrict__ Chi,
    int mode, int bm, int bn)
{
    constexpr uint32_t OFF_B   = (uint32_t)NT * TILE_B;
    constexpr uint32_t STAGE_B = (uint32_t)(NT + 1) * TILE_B;

    const int tid  = threadIdx.x;
    const int wid  = tid >> 5;
    const int lane = tid & 31;

    const int lrow = tid >> 3;
    const int lc8  = tid & 7;

    float acc[4][4][4];
#pragma unroll
    for (int mt = 0; mt < 4; mt++)
#pragma unroll
        for (int nt = 0; nt < 4; nt++)
#pragma unroll
            for (int e = 0; e < 4; e++) acc[mt][nt][e] = 0.f;

    const int mbase = (wid & 1) * 64;
    const int nbase = (wid >> 1) * 32;
    const int aRow  = mbase + (lane & 15);
    const int aKoff = (lane >> 4) * 8;
    const int bRow  = nbase + (lane & 7) + ((lane >> 4) & 1) * 8;
    const int bKoff = ((lane >> 3) & 1) * 8;
    const uint32_t aOffBase = (uint32_t)((aRow * PADK + aKoff) * 2);
    const uint32_t bOffBase = (uint32_t)((bRow * PADK + bKoff) * 2);

    auto issue = [&](int c, int st) {
        const uint32_t stb = sb + (uint32_t)st * STAGE_B;
#pragma unroll
        for (int i = 0; i < 4; i++) {
            int row = lrow + i * 32;
            uint32_t so = stb + (uint32_t)((row * PADK + lc8 * 8) * 2);
            size_t ai = (size_t)(bm + row) * 128 + c * 8 + lc8;
            size_t bi = (size_t)(bn + row) * 128 + c * 8 + lc8;
            cp16(so, pAh + ai);
            if (NT == 2) cp16(so + TILE_B, pAl + ai);
            cp16(so + OFF_B, pBh + bi);
        }
        CP_COMMIT();
    };

    issue(0, 0);
    issue(1, 1);

    for (int c = 0; c < 16; c++) {
        if (c < 15) { CP_WAIT1(); } else { CP_WAIT0(); }
        __syncthreads();
        if (c + 2 < 16) issue(c + 2, (c + 2) % 3);

        const uint32_t stb = sb + (uint32_t)(c % 3) * STAGE_B;
#pragma unroll
        for (int ks = 0; ks < 4; ks++) {
            const uint32_t kb = (uint32_t)(ks * 16 * 2);
            uint32_t bh[8];
            ldsm4(bh[0], bh[1], bh[2], bh[3], stb + OFF_B + bOffBase + kb);
            ldsm4(bh[4], bh[5], bh[6], bh[7], stb + OFF_B + bOffBase + kb + 16 * PADK * 2);
#pragma unroll
            for (int mt = 0; mt < 4; mt++) {
                const uint32_t aoff = aOffBase + (uint32_t)(mt * 16 * PADK * 2) + kb;
                uint32_t ah[4];
                ldsm4(ah[0], ah[1], ah[2], ah[3], stb + aoff);
                uint32_t al[4];
                if (NT == 2)
                    ldsm4(al[0], al[1], al[2], al[3], stb + TILE_B + aoff);
#pragma unroll
                for (int nt = 0; nt < 4; nt++) {
                    const uint32_t* bfh = &bh[(nt & 1) ? ((nt >> 1) * 4 + 2) : ((nt >> 1) * 4)];
                    mma_f16(acc[mt][nt], ah, bfh);
                    if (NT == 2) mma_f16(acc[mt][nt], al, bfh);
                }
            }
        }
    }

    const int rl = lane >> 2;
    const int cl = (lane & 3) * 2;
#pragma unroll
    for (int mt = 0; mt < 4; mt++) {
#pragma unroll
        for (int nt = 0; nt < 4; nt++) {
            const int row0 = bm + mbase + mt * 16 + rl;
            const int row1 = row0 + 8;
            const int colg = bn + nbase + nt * 8 + cl;
            float v0 = acc[mt][nt][0], v1 = acc[mt][nt][1];
            float v2 = acc[mt][nt][2], v3 = acc[mt][nt][3];
            if (mode == 0) {
                *(float2*)(C + (size_t)row0 * DD + colg) = make_float2(v0, v1);
                *(float2*)(C + (size_t)row1 * DD + colg) = make_float2(v2, v3);
            } else {
                const int h = colg >> 6, dh0 = colg & 63;
                const int b0 = row0 >> 11, s0 = row0 & 2047;
                const int b1 = row1 >> 11, s1 = row1 & 2047;
                size_t o0 = (((size_t)(b0 * HH + h)) * SS + s0) * DH + dh0;
                size_t o1 = (((size_t)(b1 * HH + h)) * SS + s1) * DH + dh0;
                *(uint32_t*)(Chi + o0) = pack_f16(v0, v1);
                *(uint32_t*)(Chi + o1) = pack_f16(v2, v3);
            }
        }
    }
}

// Fused projection GEMM (single-term fp16): z = 0 (Q), 1 (K), 2 (V).
__global__ __launch_bounds__(256) void gemm_proj(void)
{
    extern __shared__ char smem[];
    const uint32_t sb = smem_u32(smem);
    const int z = blockIdx.z;
    const uint4* pAh = (const uint4*)((z == 0) ? g_qf : (z == 1) ? g_kf : g_vf);
    const uint4* pBh = (const uint4*)g_wt[z];
    __half* Chi = (z == 0) ? g_pq : (z == 1) ? g_pk : g_pv;
    gemm_core<1>(sb, pAh, nullptr, pBh, nullptr, Chi, 3,
                 blockIdx.y * 128, blockIdx.x * 128);
}

// Output projection GEMM (single-term fp16 A = attention output).
__global__ __launch_bounds__(256) void gemm_out(float* __restrict__ C)
{
    extern __shared__ char smem[];
    const uint32_t sb = smem_u32(smem);
    gemm_core<1>(sb, (const uint4*)g_ch, nullptr, (const uint4*)g_wt[3],
                 C, nullptr, 0, blockIdx.y * 128, blockIdx.x * 128);
}

// ---------------------------------------------------------------------------
// Flash attention, mma.sync fp16, single-term QK and PV. exp2 domain
// (log2e folded into Wq). Scalar l reduction (R14 config — the l-via-MMA
// variant regressed by loading the binding tensor pipe).
// 128 threads, ATQ=64, 3-stage KV ring, Q aliases stage 2. 4 CTAs/SM.
// ---------------------------------------------------------------------------
#define ATQ  64
#define NTHR 128
#define ATK  64
#define APAD 72
#define AT_TILE (ATK*APAD*2)          // 9216
#define AST_B    (2*AT_TILE)          // 18432 per stage (K, V)
#define AKH 0
#define AVH (1*AT_TILE)
#define AQ_OFF   (2*AST_B)            // Q lives in stage 2's region
#define SMEM_ATTN (3*AST_B)           // 55296 -> 4 CTAs/SM

__global__ __launch_bounds__(NTHR) void attn_tc(
    const int* __restrict__ valid_lens_raw, __half* __restrict__ outh)
{
    extern __shared__ char smem[];
    const uint32_t sb = smem_u32(smem);
    const int tid  = threadIdx.x;
    const int w    = tid >> 5;
    const int lane = tid & 31;
    const int bh   = blockIdx.y;
    const int b    = bh >> 4;
    const int h    = bh & 15;
    const int qbase = blockIdx.x * ATQ;

    const int L = load_valid_len(valid_lens_raw, b);
    const bool uniform = (L == 0);
    const int Leff = uniform ? SS : L;
    const int ntiles = (Leff + ATK - 1) >> 6;

    const uint4* pQ = (const uint4*)g_pq;
    const uint4* pK = (const uint4*)g_pk;
    const uint4* pV = (const uint4*)g_pv;

    // ---- issue Q load into stage-2 region ----
    {
#pragma unroll
        for (int i = 0; i < 4; i++) {
            int g = tid + i * NTHR;
            int row = g >> 3, c8 = g & 7;
            size_t gi = ((size_t)bh * SS + qbase + row) * 8 + c8;
            cp16(sb + AQ_OFF + (uint32_t)((row * APAD + c8 * 8) * 2), pQ + gi);
        }
        CP_COMMIT();
    }

    auto issueKV = [&](int t, int st) {
        const uint32_t stb = sb + (uint32_t)st * AST_B;
        const int kb = t * ATK;
#pragma unroll
        for (int i = 0; i < 4; i++) {
            int g = tid + i * NTHR;
            int row = g >> 3, c8 = g & 7;
            size_t gi = ((size_t)bh * SS + kb + row) * 8 + c8;
            uint32_t so = (uint32_t)((row * APAD + c8 * 8) * 2);
            cp16(stb + AKH + so, pK + gi);
            cp16(stb + AVH + so, pV + gi);
        }
        CP_COMMIT();
    };

    issueKV(0, 0);
    if (ntiles > 1) { issueKV(1, 1); CP_WAIT2(); } else { CP_WAIT1(); }
    __syncthreads();

    // ---- Q fragments into registers (before stage 2 is overwritten) ----
    const int gid = lane >> 2;
    const int qrl = lane & 3;
    uint32_t qf[4][4];
    {
        const int aRow = w * 16 + (lane & 15);
        const uint32_t aoff0 = (uint32_t)((aRow * APAD + (lane >> 4) * 8) * 2);
#pragma unroll
        for (int ks = 0; ks < 4; ks++)
            ldsm4(qf[ks][0], qf[ks][1], qf[ks][2], qf[ks][3],
                  sb + AQ_OFF + aoff0 + (uint32_t)(ks * 16 * 2));
    }

    float O[8][4];
#pragma unroll
    for (int nt = 0; nt < 8; nt++)
#pragma unroll
        for (int e = 0; e < 4; e++) O[nt][e] = 0.f;
    float m0 = -FLT_MAX, m1 = -FLT_MAX, l0 = 0.f, l1 = 0.f;

    const int kRow = (lane & 7) + ((lane >> 4) & 1) * 8;
    const int kKof = ((lane >> 3) & 1) * 8;
    const int vRow = lane & 15;
    const int vCol = (lane >> 4) * 8;

    for (int t = 0; t < ntiles; t++) {
        if (t < ntiles - 1) { CP_WAIT1(); } else { CP_WAIT0(); }
        __syncthreads();
        if (t + 2 < ntiles) issueKV(t + 2, (t + 2) % 3);

        const uint32_t stb = sb + (uint32_t)(t % 3) * AST_B;

        // ---- scores (pre-scaled by folded Wq: log2e/8) ----
        float c[8][4];
#pragma unroll
        for (int nt = 0; nt < 8; nt++)
#pragma unroll
            for (int e = 0; e < 4; e++) c[nt][e] = 0.f;

        if (!uniform) {
#pragma unroll
            for (int ks = 0; ks < 4; ks++) {
                const uint32_t kb = (uint32_t)(ks * 16 * 2);
#pragma unroll
                for (int g = 0; g < 4; g++) {
                    const uint32_t boff = (uint32_t)(((g * 16 + kRow) * APAD + kKof) * 2) + kb;
                    uint32_t kh4[4];
                    ldsm4(kh4[0], kh4[1], kh4[2], kh4[3], stb + AKH + boff);
                    mma_f16(c[2 * g],     qf[ks], kh4 + 0);
                    mma_f16(c[2 * g + 1], qf[ks], kh4 + 2);
                }
            }
        }

        // ---- mask (last partial tile only) ----
        const int tilebase = t * ATK;
        if (tilebase + ATK > Leff) {
#pragma unroll
            for (int nt = 0; nt < 8; nt++) {
#pragma unroll
                for (int e = 0; e < 4; e++) {
                    int key = tilebase + nt * 8 + qrl * 2 + (e & 1);
                    if (key >= Leff) c[nt][e] = -FLT_MAX;
                }
            }
        }

        // ---- online softmax (base-2) ----
        float rm0 = -FLT_MAX, rm1 = -FLT_MAX;
#pragma unroll
        for (int nt = 0; nt < 8; nt++) {
            rm0 = fmaxf(rm0, fmaxf(c[nt][0], c[nt][1]));
            rm1 = fmaxf(rm1, fmaxf(c[nt][2], c[nt][3]));
        }
#pragma unroll
        for (int off = 1; off <= 2; off <<= 1) {
            rm0 = fmaxf(rm0, __shfl_xor_sync(0xffffffffu, rm0, off));
            rm1 = fmaxf(rm1, __shfl_xor_sync(0xffffffffu, rm1, off));
        }
        const float mn0 = fmaxf(m0, rm0);
        const float mn1 = fmaxf(m1, rm1);
        const float al0 = exp2f(m0 - mn0);
        const float al1 = exp2f(m1 - mn1);
        m0 = mn0; m1 = mn1;

        float ps0 = 0.f, ps1 = 0.f;
        uint32_t ph01[8], ph23[8];
#pragma unroll
        for (int nt = 0; nt < 8; nt++) {
            float p0 = exp2f(c[nt][0] - mn0);
            float p1 = exp2f(c[nt][1] - mn0);
            float p2 = exp2f(c[nt][2] - mn1);
            float p3 = exp2f(c[nt][3] - mn1);
            ps0 += p0 + p1; ps1 += p2 + p3;
            ph01[nt] = pack_f16(p0, p1);
            ph23[nt] = pack_f16(p2, p3);
        }
#pragma unroll
        for (int off = 1; off <= 2; off <<= 1) {
            ps0 += __shfl_xor_sync(0xffffffffu, ps0, off);
            ps1 += __shfl_xor_sync(0xffffffffu, ps1, off);
        }
        l0 = l0 * al0 + ps0;
        l1 = l1 * al1 + ps1;
#pragma unroll
        for (int nt = 0; nt < 8; nt++) {
            O[nt][0] *= al0; O[nt][1] *= al0;
            O[nt][2] *= al1; O[nt][3] *= al1;
        }

        // ---- O += P V ----
#pragma unroll
        for (int tk = 0; tk < 4; tk++) {
            uint32_t ah[4] = {ph01[2 * tk], ph23[2 * tk], ph01[2 * tk + 1], ph23[2 * tk + 1]};
#pragma unroll
            for (int g = 0; g < 4; g++) {
                const uint32_t voff = (uint32_t)(((tk * 16 + vRow) * APAD + g * 16 + vCol) * 2);
                uint32_t vh4[4];
                ldsm4t(vh4[0], vh4[1], vh4[2], vh4[3], stb + AVH + voff);
                mma_f16(O[2 * g],     ah, vh4 + 0);
                mma_f16(O[2 * g + 1], ah, vh4 + 2);
            }
        }
    }

    // ---- epilogue: normalize, store single fp16 concat layout ----
    const float inv0 = 1.f / l0;
    const float inv1 = 1.f / l1;
    const int q0g = qbase + w * 16 + gid;
    const int q1g = q0g + 8;
#pragma unroll
    for (int nt = 0; nt < 8; nt++) {
        const int col = h * 64 + nt * 8 + qrl * 2;
        size_t o0 = ((size_t)(b * SS + q0g)) * DD + col;
        size_t o1 = ((size_t)(b * SS + q1g)) * DD + col;
        *(uint32_t*)(outh + o0) = pack_f16(O[nt][0] * inv0, O[nt][1] * inv0);
        *(uint32_t*)(outh + o1) = pack_f16(O[nt][2] * inv1, O[nt][3] * inv1);
    }
}

// ---------------------------------------------------------------------------
extern "C" void kernel_launch(void* const* d_in, const int* in_sizes, int n_in,
                              void* d_out, int out_size)
{
    const float* Q  = (const float*)d_in[0];
    const float* Km = (const float*)d_in[1];
    const float* V  = (const float*)d_in[2];
    const int*   vl = (const int*)d_in[3];
    const float* Wq = (const float*)d_in[4];
    const float* Wk = (const float*)d_in[5];
    const float* Wv = (const float*)d_in[6];
    const float* Wo = (const float*)d_in[7];
    float* out = (float*)d_out;

    __half *ch;
    cudaGetSymbolAddress((void**)&ch, g_ch);

    cudaFuncSetAttribute(gemm_proj, cudaFuncAttributeMaxDynamicSharedMemorySize, SMEM_PROJ);
    cudaFuncSetAttribute(gemm_out,  cudaFuncAttributeMaxDynamicSharedMemorySize, SMEM_PROJ);
    cudaFuncSetAttribute(attn_tc,   cudaFuncAttributeMaxDynamicSharedMemorySize, SMEM_ATTN);

    dim3 gCvt((unsigned)(NEL / 4 / 256), 1, 3);
    cvt3_kernel<<<gCvt, 256>>>((const float4*)Q, (const float4*)Km, (const float4*)V);

    dim3 gW(32, 32, 4), bW(32, 8);
    wsplit_kernel<<<gW, bW>>>(Wq, Wk, Wv, Wo);

    dim3 gProj(DD / 128, MROWS / 128, 3);                 // (8, 64, 3)
    gemm_proj<<<gProj, 256, SMEM_PROJ>>>();

    dim3 gAttn(SS / ATQ, BB * HH);                        // (32, 64)
    attn_tc<<<gAttn, NTHR, SMEM_ATTN>>>(vl, ch);

    dim3 gOut(DD / 128, MROWS / 128);                     // (8, 64)
    gemm_out<<<gOut, 256, SMEM_PROJ>>>(out);
}